// round 2
// baseline (speedup 1.0000x reference)
#include <cuda_runtime.h>

#define N_NODES 100000
#define N_EDGES 1600000
#define F_IN 512
#define HIDDEN 16
#define N_CLASSES 40

// ---------------- scratch (no allocs allowed) ----------------
__device__ int   g_rows[N_EDGES];
__device__ int   g_cols[N_EDGES];
__device__ int   g_deg [N_NODES];
__device__ float g_dis [N_NODES];
__device__ float g_h1  [N_NODES * HIDDEN];   // x @ W1
__device__ float g_agg1[N_NODES * HIDDEN];   // scatter target, layer 1
__device__ float g_hr  [N_NODES * HIDDEN];   // relu(agg1 + b1)
__device__ float g_agg2[N_NODES * HIDDEN];   // scatter target, layer 2 (pre-W2!)
__device__ int   g_is64;

// ---------------- small helpers ----------------
__device__ __forceinline__ unsigned long long pack2(float x, float y) {
    unsigned long long r;
    asm("mov.b64 %0, {%1,%2};" : "=l"(r) : "f"(x), "f"(y));
    return r;
}
__device__ __forceinline__ float2 unpack2(unsigned long long v) {
    float2 f;
    asm("mov.b64 {%0,%1}, %2;" : "=f"(f.x), "=f"(f.y) : "l"(v));
    return f;
}
__device__ __forceinline__ void ffma2(unsigned long long& d,
                                      unsigned long long a,
                                      unsigned long long b) {
    asm("fma.rn.f32x2 %0, %1, %2, %0;" : "+l"(d) : "l"(a), "l"(b));
}
__device__ __forceinline__ void red_add_v4(float* p, float a, float b, float c, float d) {
    asm volatile("red.global.add.v4.f32 [%0], {%1,%2,%3,%4};"
                 :: "l"(p), "f"(a), "f"(b), "f"(c), "f"(d) : "memory");
}

// ---------------- degree init (self-loop = 1) ----------------
__global__ void k_deg_init() {
    int i = blockIdx.x * blockDim.x + threadIdx.x;
    if (i < N_NODES) g_deg[i] = 1;
}

// ---------------- edge_index dtype detection ----------------
// int64 little-endian values < 2^31  => every odd 32-bit word is 0.
// int32 random values in [0,100000)  => odd words are random indices (P(all 8192 zero) ~ 0).
__global__ void k_detect(const unsigned int* __restrict__ ei) {
    __shared__ unsigned int s;
    if (threadIdx.x == 0) s = 0u;
    __syncthreads();
    unsigned int v = 0;
#pragma unroll
    for (int j = 0; j < 8; j++)
        v |= ei[2 * (threadIdx.x + j * 1024) + 1];
    if (v) atomicOr(&s, 1u);
    __syncthreads();
    if (threadIdx.x == 0) g_is64 = (s == 0u) ? 1 : 0;
}

// ---------------- convert to int32 + degree count ----------------
__global__ void k_convert(const void* __restrict__ ei) {
    int e = blockIdx.x * blockDim.x + threadIdx.x;
    if (e >= N_EDGES) return;
    int r, c;
    if (g_is64) {
        const long long* p = (const long long*)ei;
        r = (int)p[e];
        c = (int)p[N_EDGES + e];
    } else {
        const int* p = (const int*)ei;
        r = p[e];
        c = p[N_EDGES + e];
    }
    g_rows[e] = r;
    g_cols[e] = c;
    atomicAdd(&g_deg[c], 1);
}

__global__ void k_dis() {
    int i = blockIdx.x * blockDim.x + threadIdx.x;
    if (i < N_NODES) g_dis[i] = rsqrtf((float)g_deg[i]);
}

// ---------------- GEMM1: h1 = x @ W1; agg1 = h1 * dis^2 (self-loop init) --------
// 128 threads/block, 1 node per thread, k-tiled through smem, FFMA2 inner loop.
__global__ void __launch_bounds__(128) k_gemm1(const float* __restrict__ x,
                                               const float* __restrict__ W1) {
    __shared__ __align__(16) float xs[128 * 33];   // padded: conflict-free scalar reads
    __shared__ __align__(16) float ws[32 * 16];
    const int t = threadIdx.x;
    const int n0 = blockIdx.x * 128;
    const int node = n0 + t;

    unsigned long long acc[8];
#pragma unroll
    for (int p = 0; p < 8; p++) acc[p] = 0ull;

    const int rbase = t >> 5;   // 0..3
    const int kk0   = t & 31;

    for (int k0 = 0; k0 < F_IN; k0 += 32) {
        // stage x tile [128 x 32], fully coalesced
#pragma unroll
        for (int i = 0; i < 32; i++) {
            int rr = i * 4 + rbase;
            int nn = n0 + rr;
            xs[rr * 33 + kk0] = (nn < N_NODES) ? x[nn * F_IN + k0 + kk0] : 0.f;
        }
        // stage W tile [32 x 16] = 512 floats = 128 float4
        ((float4*)ws)[t] = ((const float4*)(W1 + k0 * HIDDEN))[t];
        __syncthreads();

#pragma unroll
        for (int kk = 0; kk < 32; kk++) {
            float xv = xs[t * 33 + kk];
            unsigned long long xv2 = pack2(xv, xv);
            const ulonglong2* wp = (const ulonglong2*)(ws + kk * 16);
            ulonglong2 w0 = wp[0], w1 = wp[1], w2 = wp[2], w3 = wp[3];
            ffma2(acc[0], xv2, w0.x); ffma2(acc[1], xv2, w0.y);
            ffma2(acc[2], xv2, w1.x); ffma2(acc[3], xv2, w1.y);
            ffma2(acc[4], xv2, w2.x); ffma2(acc[5], xv2, w2.y);
            ffma2(acc[6], xv2, w3.x); ffma2(acc[7], xv2, w3.y);
        }
        __syncthreads();
    }

    if (node < N_NODES) {
        float d = g_dis[node];
        float d2 = d * d;
        float4* h1p = (float4*)(g_h1 + node * HIDDEN);
        float4* a1p = (float4*)(g_agg1 + node * HIDDEN);
#pragma unroll
        for (int p = 0; p < 4; p++) {
            float2 lo = unpack2(acc[2 * p]);
            float2 hi = unpack2(acc[2 * p + 1]);
            float4 v = make_float4(lo.x, lo.y, hi.x, hi.y);
            h1p[p] = v;
            a1p[p] = make_float4(v.x * d2, v.y * d2, v.z * d2, v.w * d2);
        }
    }
}

// ---------------- edge scatter (16 features, 4 lanes/edge, red.v4) ------------
template <int L>
__global__ void __launch_bounds__(256) k_scatter() {
    const float* __restrict__ src = (L == 0) ? g_h1 : g_hr;
    float* __restrict__ dst = (L == 0) ? g_agg1 : g_agg2;

    int t = blockIdx.x * blockDim.x + threadIdx.x;
    int e = t >> 2;
    if (e >= N_EDGES) return;
    int q = t & 3;
    int r = g_rows[e];
    int c = g_cols[e];
    float norm = g_dis[r] * g_dis[c];
    float4 v = *(const float4*)(src + r * HIDDEN + q * 4);
    red_add_v4(dst + c * HIDDEN + q * 4,
               v.x * norm, v.y * norm, v.z * norm, v.w * norm);
}

// ---------------- relu(agg1+b1) -> hr; agg2 = hr * dis^2 (self-loop init) -----
__global__ void k_relu(const float* __restrict__ b1) {
    int t = blockIdx.x * blockDim.x + threadIdx.x;
    if (t >= N_NODES * 4) return;
    int node = t >> 2, q = t & 3;
    float4 a = ((const float4*)g_agg1)[t];
    float4 bb = ((const float4*)b1)[q];
    float4 h;
    h.x = fmaxf(a.x + bb.x, 0.f);
    h.y = fmaxf(a.y + bb.y, 0.f);
    h.z = fmaxf(a.z + bb.z, 0.f);
    h.w = fmaxf(a.w + bb.w, 0.f);
    ((float4*)g_hr)[t] = h;
    float d = g_dis[node];
    float d2 = d * d;
    ((float4*)g_agg2)[t] = make_float4(h.x * d2, h.y * d2, h.z * d2, h.w * d2);
}

// ---------------- final: out = agg2 @ W2 + b2 (warp per node) ----------------
__global__ void __launch_bounds__(256) k_out(const float* __restrict__ W2,
                                             const float* __restrict__ b2,
                                             float* __restrict__ out) {
    __shared__ float w2s[HIDDEN * N_CLASSES];
    __shared__ float b2s[N_CLASSES];
    int t = threadIdx.x;
    for (int i = t; i < HIDDEN * N_CLASSES; i += 256) w2s[i] = W2[i];
    if (t < N_CLASSES) b2s[t] = b2[t];
    __syncthreads();

    int warp = (blockIdx.x * 256 + t) >> 5;
    int lane = t & 31;
    if (warp >= N_NODES) return;

    float a = g_agg2[warp * HIDDEN + (lane & 15)];
    float acc0 = 0.f, acc1 = 0.f;
#pragma unroll
    for (int k = 0; k < HIDDEN; k++) {
        float ak = __shfl_sync(0xffffffffu, a, k);
        acc0 += ak * w2s[k * N_CLASSES + lane];
        if (lane < 8) acc1 += ak * w2s[k * N_CLASSES + 32 + lane];
    }
    out[warp * N_CLASSES + lane] = acc0 + b2s[lane];
    if (lane < 8) out[warp * N_CLASSES + 32 + lane] = acc1 + b2s[32 + lane];
}

// ---------------- launch ----------------
extern "C" void kernel_launch(void* const* d_in, const int* in_sizes, int n_in,
                              void* d_out, int out_size) {
    const float* x  = (const float*)d_in[0];
    const void*  ei = d_in[1];
    const float* W1 = (const float*)d_in[2];
    const float* b1 = (const float*)d_in[3];
    const float* W2 = (const float*)d_in[4];
    const float* b2 = (const float*)d_in[5];
    float* out = (float*)d_out;

    k_deg_init<<<(N_NODES + 255) / 256, 256>>>();
    k_detect<<<1, 1024>>>((const unsigned int*)ei);
    k_convert<<<(N_EDGES + 255) / 256, 256>>>(ei);
    k_dis<<<(N_NODES + 255) / 256, 256>>>();
    k_gemm1<<<(N_NODES + 127) / 128, 128>>>(x, W1);
    k_scatter<0><<<(N_EDGES * 4 + 255) / 256, 256>>>();
    k_relu<<<(N_NODES * 4 + 255) / 256, 256>>>(b1);
    k_scatter<1><<<(N_EDGES * 4 + 255) / 256, 256>>>();
    // one warp per node -> need N_NODES * 32 threads (this was the round-1 bug:
    // launched N_NODES*8, leaving 75% of outputs unwritten => rel_err = sqrt(0.75))
    k_out<<<(N_NODES * 32 + 255) / 256, 256>>>(W2, b2, out);
}

// round 3
// speedup vs baseline: 1.2105x; 1.2105x over previous
#include <cuda_runtime.h>

#define N_NODES 100000
#define N_EDGES 1600000
#define F_IN 512
#define HIDDEN 16
#define N_CLASSES 40
#define NB_SCAN ((N_NODES + 1023) / 1024)   // 98

// ---------------- scratch (no device allocs allowed) ----------------
__device__ int   g_rows[N_EDGES];
__device__ int   g_cols[N_EDGES];
__device__ int   g_csr [N_EDGES];            // CSR: source node per incoming edge
__device__ int   g_ecnt[N_NODES];            // in-degree (no self loop)
__device__ int   g_fill[N_NODES];            // CSR fill cursors
__device__ int   g_start[N_NODES];           // per-block exclusive scan
__device__ int   g_blk [NB_SCAN];
__device__ int   g_blkoff[NB_SCAN];
__device__ int   g_cstart[N_NODES + 1];      // final CSR row offsets
__device__ float g_dis [N_NODES];
__device__ float g_hs1 [N_NODES * HIDDEN];   // (x@W1) * dis
__device__ float g_hs2 [N_NODES * HIDDEN];   // relu(agg1+b1) * dis
__device__ int   g_is64;

// ---------------- helpers ----------------
__device__ __forceinline__ unsigned long long pack2(float x, float y) {
    unsigned long long r;
    asm("mov.b64 %0, {%1,%2};" : "=l"(r) : "f"(x), "f"(y));
    return r;
}
__device__ __forceinline__ float2 unpack2(unsigned long long v) {
    float2 f;
    asm("mov.b64 {%0,%1}, %2;" : "=f"(f.x), "=f"(f.y) : "l"(v));
    return f;
}
__device__ __forceinline__ void ffma2(unsigned long long& d,
                                      unsigned long long a,
                                      unsigned long long b) {
    asm("fma.rn.f32x2 %0, %1, %2, %0;" : "+l"(d) : "l"(a), "l"(b));
}
__device__ __forceinline__ float4 f4add(float4 a, float4 b) {
    return make_float4(a.x + b.x, a.y + b.y, a.z + b.z, a.w + b.w);
}

// ---------------- init counters ----------------
__global__ void k_init() {
    int i = blockIdx.x * blockDim.x + threadIdx.x;
    if (i < N_NODES) { g_ecnt[i] = 0; g_fill[i] = 0; }
}

// ---------------- edge_index dtype detection ----------------
// int64 LE values < 2^31 => every odd 32-bit word is 0; int32 random => not.
__global__ void k_detect(const unsigned int* __restrict__ ei) {
    __shared__ unsigned int s;
    if (threadIdx.x == 0) s = 0u;
    __syncthreads();
    unsigned int v = 0;
#pragma unroll
    for (int j = 0; j < 8; j++)
        v |= ei[2 * (threadIdx.x + j * 1024) + 1];
    if (v) atomicOr(&s, 1u);
    __syncthreads();
    if (threadIdx.x == 0) g_is64 = (s == 0u) ? 1 : 0;
}

// ---------------- convert to int32 + in-degree count ----------------
__global__ void k_convert(const void* __restrict__ ei) {
    int e = blockIdx.x * blockDim.x + threadIdx.x;
    if (e >= N_EDGES) return;
    int r, c;
    if (g_is64) {
        const long long* p = (const long long*)ei;
        r = (int)p[e];
        c = (int)p[N_EDGES + e];
    } else {
        const int* p = (const int*)ei;
        r = p[e];
        c = p[N_EDGES + e];
    }
    g_rows[e] = r;
    g_cols[e] = c;
    atomicAdd(&g_ecnt[c], 1);
}

__global__ void k_dis() {
    int i = blockIdx.x * blockDim.x + threadIdx.x;
    if (i < N_NODES) g_dis[i] = rsqrtf((float)(g_ecnt[i] + 1));  // +1 self-loop
}

// ---------------- 2-level exclusive scan of g_ecnt -> g_cstart ----------------
__global__ void __launch_bounds__(1024) k_scan1() {
    __shared__ int s[1024];
    int i = blockIdx.x * 1024 + threadIdx.x;
    int v = (i < N_NODES) ? g_ecnt[i] : 0;
    s[threadIdx.x] = v;
    __syncthreads();
#pragma unroll
    for (int off = 1; off < 1024; off <<= 1) {
        int t = (threadIdx.x >= off) ? s[threadIdx.x - off] : 0;
        __syncthreads();
        s[threadIdx.x] += t;
        __syncthreads();
    }
    int inc = s[threadIdx.x];
    if (i < N_NODES) g_start[i] = inc - v;          // exclusive
    if (threadIdx.x == 1023) g_blk[blockIdx.x] = inc;
}

__global__ void k_scan2() {
    if (threadIdx.x == 0) {
        int acc = 0;
        for (int i = 0; i < NB_SCAN; i++) {
            int t = g_blk[i];
            g_blkoff[i] = acc;
            acc += t;
        }
    }
}

__global__ void k_finalize() {
    int i = blockIdx.x * blockDim.x + threadIdx.x;
    if (i < N_NODES) g_cstart[i] = g_start[i] + g_blkoff[i >> 10];
    if (i == 0) g_cstart[N_NODES] = N_EDGES;
}

// ---------------- CSR fill (bucket scatter of source indices) ----------------
__global__ void k_fill() {
    int e = blockIdx.x * blockDim.x + threadIdx.x;
    if (e >= N_EDGES) return;
    int r = g_rows[e];
    int c = g_cols[e];
    int pos = g_cstart[c] + atomicAdd(&g_fill[c], 1);
    g_csr[pos] = r;
}

// ---------------- GEMM1: hs1 = (x @ W1) * dis ----------------
__global__ void __launch_bounds__(128) k_gemm1(const float* __restrict__ x,
                                               const float* __restrict__ W1) {
    __shared__ __align__(16) float xs[128 * 33];
    __shared__ __align__(16) float ws[32 * 16];
    const int t = threadIdx.x;
    const int n0 = blockIdx.x * 128;
    const int node = n0 + t;

    unsigned long long acc[8];
#pragma unroll
    for (int p = 0; p < 8; p++) acc[p] = 0ull;

    const int rbase = t >> 5;
    const int kk0   = t & 31;

    for (int k0 = 0; k0 < F_IN; k0 += 32) {
#pragma unroll
        for (int i = 0; i < 32; i++) {
            int rr = i * 4 + rbase;
            int nn = n0 + rr;
            xs[rr * 33 + kk0] = (nn < N_NODES) ? x[nn * F_IN + k0 + kk0] : 0.f;
        }
        ((float4*)ws)[t] = ((const float4*)(W1 + k0 * HIDDEN))[t];
        __syncthreads();

#pragma unroll
        for (int kk = 0; kk < 32; kk++) {
            float xv = xs[t * 33 + kk];
            unsigned long long xv2 = pack2(xv, xv);
            const ulonglong2* wp = (const ulonglong2*)(ws + kk * 16);
            ulonglong2 w0 = wp[0], w1 = wp[1], w2 = wp[2], w3 = wp[3];
            ffma2(acc[0], xv2, w0.x); ffma2(acc[1], xv2, w0.y);
            ffma2(acc[2], xv2, w1.x); ffma2(acc[3], xv2, w1.y);
            ffma2(acc[4], xv2, w2.x); ffma2(acc[5], xv2, w2.y);
            ffma2(acc[6], xv2, w3.x); ffma2(acc[7], xv2, w3.y);
        }
        __syncthreads();
    }

    if (node < N_NODES) {
        float d = g_dis[node];
        float4* hp = (float4*)(g_hs1 + node * HIDDEN);
#pragma unroll
        for (int p = 0; p < 4; p++) {
            float2 lo = unpack2(acc[2 * p]);
            float2 hi = unpack2(acc[2 * p + 1]);
            hp[p] = make_float4(lo.x * d, lo.y * d, hi.x * d, hi.y * d);
        }
    }
}

// ---------------- gather core (4 threads per node, float4 per thread) ---------
__device__ __forceinline__ float4 gather_acc(const float4* __restrict__ src,
                                             int node, int q) {
    int beg = g_cstart[node];
    int end = g_cstart[node + 1];
    float4 acc = make_float4(0.f, 0.f, 0.f, 0.f);
    int e = beg;
    for (; e + 4 <= end; e += 4) {
        int r0 = g_csr[e], r1 = g_csr[e + 1], r2 = g_csr[e + 2], r3 = g_csr[e + 3];
        float4 v0 = src[r0 * 4 + q];
        float4 v1 = src[r1 * 4 + q];
        float4 v2 = src[r2 * 4 + q];
        float4 v3 = src[r3 * 4 + q];
        acc = f4add(acc, f4add(f4add(v0, v1), f4add(v2, v3)));
    }
    for (; e < end; e++)
        acc = f4add(acc, src[g_csr[e] * 4 + q]);
    return acc;
}

// ---------------- layer1 gather: hs2 = relu(dis*(sum+hs1_self) + b1) * dis ----
__global__ void __launch_bounds__(256) k_gather1(const float* __restrict__ b1) {
    int t = blockIdx.x * blockDim.x + threadIdx.x;
    int node = t >> 2;
    if (node >= N_NODES) return;
    int q = t & 3;
    const float4* src = (const float4*)g_hs1;
    float4 acc = gather_acc(src, node, q);
    float4 self = src[node * 4 + q];
    float d = g_dis[node];
    float4 bb = ((const float4*)b1)[q];
    float4 h;
    h.x = fmaxf(fmaf(acc.x + self.x, d, bb.x), 0.f) * d;
    h.y = fmaxf(fmaf(acc.y + self.y, d, bb.y), 0.f) * d;
    h.z = fmaxf(fmaf(acc.z + self.z, d, bb.z), 0.f) * d;
    h.w = fmaxf(fmaf(acc.w + self.w, d, bb.w), 0.f) * d;
    ((float4*)g_hs2)[node * 4 + q] = h;
}

// ---------------- layer2 gather fused with @W2 + b2 -> out ----------------
__global__ void __launch_bounds__(256) k_gather2(const float* __restrict__ W2,
                                                 const float* __restrict__ b2,
                                                 float* __restrict__ out) {
    __shared__ float w2s[HIDDEN * N_CLASSES];
    __shared__ float b2s[N_CLASSES];
    {
        int tt = threadIdx.x;
        for (int i = tt; i < HIDDEN * N_CLASSES; i += 256) w2s[i] = W2[i];
        if (tt < N_CLASSES) b2s[tt] = b2[tt];
        __syncthreads();
    }
    int t = blockIdx.x * blockDim.x + threadIdx.x;
    int node = t >> 2;
    bool valid = (node < N_NODES);
    int node_c = valid ? node : 0;          // clamp; all lanes run the shuffles
    int q = t & 3;
    int lane = threadIdx.x & 31;
    int qbase = lane & ~3;

    const float4* src = (const float4*)g_hs2;
    float4 acc = gather_acc(src, node_c, q);
    float4 self = src[node_c * 4 + q];
    float d = g_dis[node_c];
    float av[4];
    av[0] = (acc.x + self.x) * d;
    av[1] = (acc.y + self.y) * d;
    av[2] = (acc.z + self.z) * d;
    av[3] = (acc.w + self.w) * d;

    // out_j = sum_k agg2[k] * W2[k][j], thread q computes j = q + 4*t10
    float o[10];
#pragma unroll
    for (int j = 0; j < 10; j++) o[j] = b2s[q + 4 * j];

#pragma unroll
    for (int p = 0; p < 4; p++) {
#pragma unroll
        for (int comp = 0; comp < 4; comp++) {
            float v = __shfl_sync(0xffffffffu, av[comp], qbase + p);
            int k = p * 4 + comp;
#pragma unroll
            for (int j = 0; j < 10; j++)
                o[j] = fmaf(v, w2s[k * N_CLASSES + q + 4 * j], o[j]);
        }
    }
    if (valid) {
#pragma unroll
        for (int j = 0; j < 10; j++)
            out[node * N_CLASSES + q + 4 * j] = o[j];
    }
}

// ---------------- launch ----------------
extern "C" void kernel_launch(void* const* d_in, const int* in_sizes, int n_in,
                              void* d_out, int out_size) {
    const float* x  = (const float*)d_in[0];
    const void*  ei = d_in[1];
    const float* W1 = (const float*)d_in[2];
    const float* b1 = (const float*)d_in[3];
    const float* W2 = (const float*)d_in[4];
    const float* b2 = (const float*)d_in[5];
    float* out = (float*)d_out;

    k_init<<<(N_NODES + 255) / 256, 256>>>();
    k_detect<<<1, 1024>>>((const unsigned int*)ei);
    k_convert<<<(N_EDGES + 255) / 256, 256>>>(ei);
    k_dis<<<(N_NODES + 255) / 256, 256>>>();
    k_scan1<<<NB_SCAN, 1024>>>();
    k_scan2<<<1, 32>>>();
    k_finalize<<<(N_NODES + 255) / 256, 256>>>();
    k_fill<<<(N_EDGES + 255) / 256, 256>>>();
    k_gemm1<<<(N_NODES + 127) / 128, 128>>>(x, W1);
    k_gather1<<<(N_NODES * 4 + 255) / 256, 256>>>(b1);
    k_gather2<<<(N_NODES * 4 + 255) / 256, 256>>>(W2, b2, out);
}

// round 4
// speedup vs baseline: 1.4169x; 1.1705x over previous
#include <cuda_runtime.h>

#define N_NODES 100000
#define N_EDGES 1600000
#define F_IN 512
#define HIDDEN 16
#define N_CLASSES 40
#define NB_SCAN ((N_NODES + 1023) / 1024)   // 98

// ---------------- scratch (no device allocs allowed) ----------------
__device__ int   g_csr [N_EDGES];            // CSR: source node per incoming edge
__device__ int   g_ecnt[N_NODES];            // in-degree (no self loop)
__device__ int   g_fill[N_NODES];            // CSR fill cursors
__device__ int   g_start[N_NODES];           // per-block exclusive scan
__device__ int   g_blk [NB_SCAN];
__device__ int   g_blkoff[NB_SCAN];
__device__ int   g_cstart[N_NODES + 1];      // final CSR row offsets
__device__ float g_dis [N_NODES];
__device__ float g_hs1 [N_NODES * HIDDEN];   // x@W1 (then *dis after k_scale)
__device__ float g_hs2 [N_NODES * HIDDEN];   // relu(agg1+b1) * dis
__device__ int   g_is64;

// ---------------- helpers ----------------
__device__ __forceinline__ unsigned long long pack2(float x, float y) {
    unsigned long long r;
    asm("mov.b64 %0, {%1,%2};" : "=l"(r) : "f"(x), "f"(y));
    return r;
}
__device__ __forceinline__ float2 unpack2(unsigned long long v) {
    float2 f;
    asm("mov.b64 {%0,%1}, %2;" : "=f"(f.x), "=f"(f.y) : "l"(v));
    return f;
}
__device__ __forceinline__ void ffma2(unsigned long long& d,
                                      unsigned long long a,
                                      unsigned long long b) {
    asm("fma.rn.f32x2 %0, %1, %2, %0;" : "+l"(d) : "l"(a), "l"(b));
}
__device__ __forceinline__ float4 f4add(float4 a, float4 b) {
    return make_float4(a.x + b.x, a.y + b.y, a.z + b.z, a.w + b.w);
}

// ---------------- edge_index dtype detection ----------------
// int64 LE values < 2^31 => every odd 32-bit word is 0; int32 random => not.
__global__ void k_detect(const unsigned int* __restrict__ ei) {
    __shared__ unsigned int s;
    if (threadIdx.x == 0) s = 0u;
    __syncthreads();
    unsigned int v = 0;
#pragma unroll
    for (int j = 0; j < 8; j++)
        v |= ei[2 * (threadIdx.x + j * 1024) + 1];
    if (v) atomicOr(&s, 1u);
    __syncthreads();
    if (threadIdx.x == 0) g_is64 = (s == 0u) ? 1 : 0;
}

__device__ __forceinline__ int load_col(const void* ei, int e) {
    return g_is64 ? (int)((const long long*)ei)[N_EDGES + e]
                  : ((const int*)ei)[N_EDGES + e];
}
__device__ __forceinline__ int load_row(const void* ei, int e) {
    return g_is64 ? (int)((const long long*)ei)[e]
                  : ((const int*)ei)[e];
}

// ---------------- in-degree count (reads col half of edge_index) -------------
__global__ void k_count(const void* __restrict__ ei) {
    int e = blockIdx.x * blockDim.x + threadIdx.x;
    if (e >= N_EDGES) return;
    atomicAdd(&g_ecnt[load_col(ei, e)], 1);
}

// ---------------- block scan (warp shuffles) + dis = rsqrt(deg+1) ------------
__global__ void __launch_bounds__(1024) k_scan1() {
    __shared__ int wsum[32];
    int i = blockIdx.x * 1024 + threadIdx.x;
    int v = (i < N_NODES) ? g_ecnt[i] : 0;
    if (i < N_NODES) g_dis[i] = rsqrtf((float)(v + 1));
    int lane = threadIdx.x & 31;
    int warp = threadIdx.x >> 5;
    int incl = v;
#pragma unroll
    for (int o = 1; o < 32; o <<= 1) {
        int t = __shfl_up_sync(0xffffffffu, incl, o);
        if (lane >= o) incl += t;
    }
    if (lane == 31) wsum[warp] = incl;
    __syncthreads();
    if (warp == 0) {
        int s = wsum[lane];
#pragma unroll
        for (int o = 1; o < 32; o <<= 1) {
            int t = __shfl_up_sync(0xffffffffu, s, o);
            if (lane >= o) s += t;
        }
        wsum[lane] = s;
    }
    __syncthreads();
    int off = (warp > 0) ? wsum[warp - 1] : 0;
    incl += off;
    if (i < N_NODES) g_start[i] = incl - v;   // block-local exclusive
    if (threadIdx.x == 1023) g_blk[blockIdx.x] = incl;
}

// ---------------- scan of block sums (parallel, one block) -------------------
__global__ void __launch_bounds__(128) k_scan2() {
    __shared__ int s[128];
    int i = threadIdx.x;
    int v = (i < NB_SCAN) ? g_blk[i] : 0;
    s[i] = v;
    __syncthreads();
#pragma unroll
    for (int o = 1; o < 128; o <<= 1) {
        int t = (i >= o) ? s[i - o] : 0;
        __syncthreads();
        s[i] += t;
        __syncthreads();
    }
    if (i < NB_SCAN) g_blkoff[i] = s[i] - v;  // exclusive
}

__global__ void k_finalize() {
    int i = blockIdx.x * blockDim.x + threadIdx.x;
    if (i < N_NODES) g_cstart[i] = g_start[i] + g_blkoff[i >> 10];
    if (i == 0) g_cstart[N_NODES] = N_EDGES;
}

// ---------------- CSR fill (decodes edge_index directly) ---------------------
__global__ void k_fill(const void* __restrict__ ei) {
    int e = blockIdx.x * blockDim.x + threadIdx.x;
    if (e >= N_EDGES) return;
    int r = load_row(ei, e);
    int c = load_col(ei, e);
    int pos = g_cstart[c] + atomicAdd(&g_fill[c], 1);
    g_csr[pos] = r;
}

// ---------------- GEMM1: hs1 = x @ W1 (unscaled; runs on side stream) --------
__global__ void __launch_bounds__(128) k_gemm1(const float* __restrict__ x,
                                               const float* __restrict__ W1) {
    __shared__ __align__(16) float xs[128 * 33];
    __shared__ __align__(16) float ws[32 * 16];
    const int t = threadIdx.x;
    const int n0 = blockIdx.x * 128;
    const int node = n0 + t;

    unsigned long long acc[8];
#pragma unroll
    for (int p = 0; p < 8; p++) acc[p] = 0ull;

    const int rbase = t >> 5;
    const int kk0   = t & 31;

    for (int k0 = 0; k0 < F_IN; k0 += 32) {
#pragma unroll
        for (int i = 0; i < 32; i++) {
            int rr = i * 4 + rbase;
            int nn = n0 + rr;
            xs[rr * 33 + kk0] = (nn < N_NODES) ? x[nn * F_IN + k0 + kk0] : 0.f;
        }
        ((float4*)ws)[t] = ((const float4*)(W1 + k0 * HIDDEN))[t];
        __syncthreads();

#pragma unroll
        for (int kk = 0; kk < 32; kk++) {
            float xv = xs[t * 33 + kk];
            unsigned long long xv2 = pack2(xv, xv);
            const ulonglong2* wp = (const ulonglong2*)(ws + kk * 16);
            ulonglong2 w0 = wp[0], w1 = wp[1], w2 = wp[2], w3 = wp[3];
            ffma2(acc[0], xv2, w0.x); ffma2(acc[1], xv2, w0.y);
            ffma2(acc[2], xv2, w1.x); ffma2(acc[3], xv2, w1.y);
            ffma2(acc[4], xv2, w2.x); ffma2(acc[5], xv2, w2.y);
            ffma2(acc[6], xv2, w3.x); ffma2(acc[7], xv2, w3.y);
        }
        __syncthreads();
    }

    if (node < N_NODES) {
        float4* hp = (float4*)(g_hs1 + node * HIDDEN);
#pragma unroll
        for (int p = 0; p < 4; p++) {
            float2 lo = unpack2(acc[2 * p]);
            float2 hi = unpack2(acc[2 * p + 1]);
            hp[p] = make_float4(lo.x, lo.y, hi.x, hi.y);
        }
    }
}

// ---------------- hs1 *= dis (join point after fork) -------------------------
__global__ void k_scale() {
    int t = blockIdx.x * blockDim.x + threadIdx.x;
    if (t >= N_NODES * 4) return;
    float d = g_dis[t >> 2];
    float4 v = ((float4*)g_hs1)[t];
    ((float4*)g_hs1)[t] = make_float4(v.x * d, v.y * d, v.z * d, v.w * d);
}

// ---------------- gather core: 4 threads/node, shuffled shared indices -------
__device__ __forceinline__ float4 gather_acc(const float4* __restrict__ src,
                                             int node, int q,
                                             unsigned qmask, int qbase) {
    int beg = g_cstart[node];
    int end = g_cstart[node + 1];
    float4 acc = make_float4(0.f, 0.f, 0.f, 0.f);
    int e = beg;
    for (; e + 4 <= end; e += 4) {
        int myi = g_csr[e + q];                       // one index load per lane
        int r0 = __shfl_sync(qmask, myi, qbase + 0);
        int r1 = __shfl_sync(qmask, myi, qbase + 1);
        int r2 = __shfl_sync(qmask, myi, qbase + 2);
        int r3 = __shfl_sync(qmask, myi, qbase + 3);
        float4 v0 = src[r0 * 4 + q];
        float4 v1 = src[r1 * 4 + q];
        float4 v2 = src[r2 * 4 + q];
        float4 v3 = src[r3 * 4 + q];
        acc = f4add(acc, f4add(f4add(v0, v1), f4add(v2, v3)));
    }
    int rem = end - e;
    if (rem > 0) {
        int myi = (q < rem) ? g_csr[e + q] : 0;
        for (int j = 0; j < rem; j++) {
            int r = __shfl_sync(qmask, myi, qbase + j);
            acc = f4add(acc, src[r * 4 + q]);
        }
    }
    return acc;
}

// ---------------- layer1 gather: hs2 = relu(dis*(sum+self) + b1) * dis -------
__global__ void __launch_bounds__(256) k_gather1(const float* __restrict__ b1) {
    int t = blockIdx.x * blockDim.x + threadIdx.x;
    int node = t >> 2;
    if (node >= N_NODES) return;
    int q = t & 3;
    int qbase = (threadIdx.x & 31) & ~3;
    unsigned qmask = 0xFu << qbase;
    const float4* src = (const float4*)g_hs1;
    float4 acc = gather_acc(src, node, q, qmask, qbase);
    float4 self = src[node * 4 + q];
    float d = g_dis[node];
    float4 bb = ((const float4*)b1)[q];
    float4 h;
    h.x = fmaxf(fmaf(acc.x + self.x, d, bb.x), 0.f) * d;
    h.y = fmaxf(fmaf(acc.y + self.y, d, bb.y), 0.f) * d;
    h.z = fmaxf(fmaf(acc.z + self.z, d, bb.z), 0.f) * d;
    h.w = fmaxf(fmaf(acc.w + self.w, d, bb.w), 0.f) * d;
    ((float4*)g_hs2)[node * 4 + q] = h;
}

// ---------------- layer2 gather fused with @W2 + b2 -> out -------------------
__global__ void __launch_bounds__(256) k_gather2(const float* __restrict__ W2,
                                                 const float* __restrict__ b2,
                                                 float* __restrict__ out) {
    __shared__ float w2s[HIDDEN * N_CLASSES];
    __shared__ float b2s[N_CLASSES];
    {
        int tt = threadIdx.x;
        for (int i = tt; i < HIDDEN * N_CLASSES; i += 256) w2s[i] = W2[i];
        if (tt < N_CLASSES) b2s[tt] = b2[tt];
        __syncthreads();
    }
    int t = blockIdx.x * blockDim.x + threadIdx.x;
    int node = t >> 2;
    bool valid = (node < N_NODES);
    int node_c = valid ? node : 0;
    int q = t & 3;
    int lane = threadIdx.x & 31;
    int qbase = lane & ~3;
    unsigned qmask = 0xFu << qbase;

    const float4* src = (const float4*)g_hs2;
    float4 acc = gather_acc(src, node_c, q, qmask, qbase);
    float4 self = src[node_c * 4 + q];
    float d = g_dis[node_c];
    float av[4];
    av[0] = (acc.x + self.x) * d;
    av[1] = (acc.y + self.y) * d;
    av[2] = (acc.z + self.z) * d;
    av[3] = (acc.w + self.w) * d;

    float o[10];
#pragma unroll
    for (int j = 0; j < 10; j++) o[j] = b2s[q + 4 * j];

#pragma unroll
    for (int p = 0; p < 4; p++) {
#pragma unroll
        for (int comp = 0; comp < 4; comp++) {
            float v = __shfl_sync(0xffffffffu, av[comp], qbase + p);
            int k = p * 4 + comp;
#pragma unroll
            for (int j = 0; j < 10; j++)
                o[j] = fmaf(v, w2s[k * N_CLASSES + q + 4 * j], o[j]);
        }
    }
    if (valid) {
#pragma unroll
        for (int j = 0; j < 10; j++)
            out[node * N_CLASSES + q + 4 * j] = o[j];
    }
}

// ---------------- launch ----------------
extern "C" void kernel_launch(void* const* d_in, const int* in_sizes, int n_in,
                              void* d_out, int out_size) {
    const float* x  = (const float*)d_in[0];
    const void*  ei = d_in[1];
    const float* W1 = (const float*)d_in[2];
    const float* b1 = (const float*)d_in[3];
    const float* W2 = (const float*)d_in[4];
    const float* b2 = (const float*)d_in[5];
    float* out = (float*)d_out;

    // zero counters via async memset (capturable, no alloc)
    void *p_ecnt = nullptr, *p_fill = nullptr;
    cudaGetSymbolAddress(&p_ecnt, g_ecnt);
    cudaGetSymbolAddress(&p_fill, g_fill);
    cudaMemsetAsync(p_ecnt, 0, N_NODES * sizeof(int), 0);
    cudaMemsetAsync(p_fill, 0, N_NODES * sizeof(int), 0);

    // fork: GEMM1 (independent of edge chain) on a side stream
    cudaStream_t s2;
    cudaStreamCreateWithFlags(&s2, cudaStreamNonBlocking);
    cudaEvent_t evA, evB;
    cudaEventCreateWithFlags(&evA, cudaEventDisableTiming);
    cudaEventCreateWithFlags(&evB, cudaEventDisableTiming);
    cudaEventRecord(evA, 0);
    cudaStreamWaitEvent(s2, evA, 0);
    k_gemm1<<<(N_NODES + 127) / 128, 128, 0, s2>>>(x, W1);
    cudaEventRecord(evB, s2);

    // edge chain on the main (capture) stream
    k_detect<<<1, 1024>>>((const unsigned int*)ei);
    k_count<<<(N_EDGES + 255) / 256, 256>>>(ei);
    k_scan1<<<NB_SCAN, 1024>>>();
    k_scan2<<<1, 128>>>();
    k_finalize<<<(N_NODES + 255) / 256, 256>>>();
    k_fill<<<(N_EDGES + 255) / 256, 256>>>(ei);

    // join, then scaled gathers
    cudaStreamWaitEvent(0, evB, 0);
    k_scale<<<(N_NODES * 4 + 255) / 256, 256>>>();
    k_gather1<<<(N_NODES * 4 + 255) / 256, 256>>>(b1);
    k_gather2<<<(N_NODES * 4 + 255) / 256, 256>>>(W2, b2, out);

    cudaEventDestroy(evA);
    cudaEventDestroy(evB);
    cudaStreamDestroy(s2);
}